// round 6
// baseline (speedup 1.0000x reference)
#include <cuda_runtime.h>
#include <cstdint>

// Batched NT GEMM via tensor-core mma.sync (TF32) + cp.async pipeline:
//   C[b,i,j] = sum_d A[b,i,d] * B[b,j,d]
// A,B: [16,1024,256] f32 row-major, C: [16,1024,1024] f32.
//
// CTA 128(M)x256(N), 8 warps (2M x 4N), warp tile 64x64 (halves smem
// fragment bytes per HMMA vs 64x32). BK=32, 3-stage cp.async ring,
// double-buffered ldmatrix fragments across kc. Raw f32 in SMEM; HW mma
// truncates to TF32; epilogue multiplies by 1.0007047 to cancel the bias.

#define BATCH 16
#define RDIM  1024
#define DDIM  256

#define BM 128
#define BN 256
#define BK 32
#define STAGES 3
#define KTILES (DDIM / BK)   // 8
#define NTHREADS 256

#define A_STAGE_B 16384                       // 128 rows x 128B
#define B_STAGE_B 32768                       // 256 rows x 128B
#define B_BASE    (STAGES * A_STAGE_B)        // 49152
#define SMEM_TOTAL (STAGES * (A_STAGE_B + B_STAGE_B))  // 147456

// TF32 truncation-bias correction (see R5): scale C by (1 + 7.047e-4).
#define CORR 1.0007047f

__device__ __forceinline__ uint32_t smem_u32(const void* p) {
    uint32_t a;
    asm("{ .reg .u64 t; cvta.to.shared.u64 t, %1; cvt.u32.u64 %0, t; }" : "=r"(a) : "l"(p));
    return a;
}

__device__ __forceinline__ void cp_async16(uint32_t dst, const void* src) {
    asm volatile("cp.async.cg.shared.global [%0], [%1], 16;" :: "r"(dst), "l"(src) : "memory");
}
__device__ __forceinline__ void cp_commit() {
    asm volatile("cp.async.commit_group;" ::: "memory");
}
__device__ __forceinline__ void cp_wait1() {
    asm volatile("cp.async.wait_group 1;" ::: "memory");
}

__device__ __forceinline__ void ldsm4(uint32_t* d, uint32_t addr) {
    asm volatile("ldmatrix.sync.aligned.m8n8.x4.shared.b16 {%0,%1,%2,%3}, [%4];"
                 : "=r"(d[0]), "=r"(d[1]), "=r"(d[2]), "=r"(d[3]) : "r"(addr));
}

__device__ __forceinline__ void mma_tf32(float* c, const uint32_t* a, const uint32_t* b) {
    asm volatile(
        "mma.sync.aligned.m16n8k8.row.col.f32.tf32.tf32.f32 "
        "{%0,%1,%2,%3}, {%4,%5,%6,%7}, {%8,%9}, {%0,%1,%2,%3};"
        : "+f"(c[0]), "+f"(c[1]), "+f"(c[2]), "+f"(c[3])
        : "r"(a[0]), "r"(a[1]), "r"(a[2]), "r"(a[3]), "r"(b[0]), "r"(b[1]));
}

__global__ void __launch_bounds__(NTHREADS, 1)
bgemm_tf32_cpasync64_kernel(const float* __restrict__ A,
                            const float* __restrict__ B,
                            float* __restrict__ C)
{
    extern __shared__ char smem[];
    const uint32_t sb = smem_u32(smem);

    const int tid  = threadIdx.x;
    const int wid  = tid >> 5;
    const int lane = tid & 31;

    const int b  = blockIdx.z;
    const int m0 = blockIdx.y * BM;
    const int n0 = blockIdx.x * BN;

    // ---- cp.async loader constants ----
    // Per stage: A 128x32 f32 = 1024 x16B (4/thread); B 256x32 = 2048 x16B (8/thread).
    const int lrow = tid >> 3;       // 0..31
    const int lc4  = tid & 7;        // 16B unit within 128B row
    const float* gA = A + ((size_t)b * RDIM + m0 + lrow) * DDIM + lc4 * 4;
    const float* gB = B + ((size_t)b * RDIM + n0 + lrow) * DDIM + lc4 * 4;
    const uint32_t swu = (uint32_t)(lc4 ^ (lrow & 7)) << 4;     // SW128
    const uint32_t sA0 = sb + lrow * 128 + swu;
    const uint32_t sB0 = sb + B_BASE + lrow * 128 + swu;

    // ---- MMA constants ----
    const int warp_m = (wid & 1) * 64;       // 2 warps along M
    const int warp_n = (wid >> 1) * 64;      // 4 warps along N
    const int q  = lane >> 3;
    const int r_ = lane & 7;
    const int a_moff = (q & 1) * 8 + r_;
    const int a_par  = q >> 1;
    const int b_noff = (q >> 1) * 8 + r_;
    const int b_par  = q & 1;
    const uint32_t aF0 = sb + (warp_m + a_moff) * 128;
    const uint32_t bF0 = sb + B_BASE + (warp_n + b_noff) * 128;

    float acc[4][8][4];
    #pragma unroll
    for (int i = 0; i < 4; i++)
        #pragma unroll
        for (int j = 0; j < 8; j++)
            #pragma unroll
            for (int k = 0; k < 4; k++)
                acc[i][j][k] = 0.0f;

#define ISSUE_STAGE(s, ko)                                                     \
    do {                                                                       \
        const uint32_t _a = sA0 + (s) * A_STAGE_B;                             \
        const uint32_t _b = sB0 + (s) * B_STAGE_B;                             \
        _Pragma("unroll")                                                      \
        for (int _i = 0; _i < 4; _i++)                                         \
            cp_async16(_a + _i * 4096, gA + (size_t)_i * 32 * DDIM + (ko));    \
        _Pragma("unroll")                                                      \
        for (int _i = 0; _i < 8; _i++)                                         \
            cp_async16(_b + _i * 4096, gB + (size_t)_i * 32 * DDIM + (ko));    \
    } while (0)

    // fragment load for one kc into buffer p
    uint32_t af[2][4][4], bf[2][4][4];
#define LD_FRAGS(p, aBase, bBase, kc)                                          \
    do {                                                                       \
        const uint32_t _ua = ((uint32_t)((2 * (kc) + a_par) ^ r_)) << 4;       \
        const uint32_t _ub = ((uint32_t)((2 * (kc) + b_par) ^ r_)) << 4;       \
        _Pragma("unroll")                                                      \
        for (int _mt = 0; _mt < 4; _mt++)                                      \
            ldsm4(af[p][_mt], (aBase) + _mt * 2048 + _ua);                     \
        _Pragma("unroll")                                                      \
        for (int _np = 0; _np < 4; _np++)                                      \
            ldsm4(bf[p][_np], (bBase) + _np * 2048 + _ub);                     \
    } while (0)

#define MMA_ALL(p)                                                             \
    do {                                                                       \
        _Pragma("unroll")                                                      \
        for (int _mt = 0; _mt < 4; _mt++)                                      \
            _Pragma("unroll")                                                  \
            for (int _nt = 0; _nt < 8; _nt++)                                  \
                mma_tf32(acc[_mt][_nt], af[p][_mt], &bf[p][_nt >> 1][(_nt & 1) * 2]); \
    } while (0)

    // ---- prologue: stages 0,1 in flight ----
    ISSUE_STAGE(0, 0);
    cp_commit();
    ISSUE_STAGE(1, BK);
    cp_commit();

    int s = 0;
    for (int kt = 0; kt < KTILES; kt++) {
        cp_wait1();          // stage kt landed
        __syncthreads();     // visible to all warps; stage (kt-1) fully consumed

        if (kt < KTILES - 2)
            ISSUE_STAGE((kt + 2) % STAGES, (kt + 2) * BK);
        cp_commit();         // uniform group count

        const uint32_t aBase = aF0 + s * A_STAGE_B;
        const uint32_t bBase = bF0 + s * B_STAGE_B;

        // software-pipelined fragments: ldsm(kc+1) issued before mma(kc)
        LD_FRAGS(0, aBase, bBase, 0);
        #pragma unroll
        for (int kc = 0; kc < 4; kc++) {
            if (kc < 3)
                LD_FRAGS((kc + 1) & 1, aBase, bBase, kc + 1);
            MMA_ALL(kc & 1);
        }

        s = (s + 1 == STAGES) ? 0 : s + 1;
    }

    // ---- epilogue: bias-corrected stores ----
    const int g = lane >> 2;
    const int t = lane & 3;
    float* Cw = C + (size_t)b * RDIM * RDIM + (size_t)(m0 + warp_m) * RDIM + n0 + warp_n;

    #pragma unroll
    for (int mt = 0; mt < 4; mt++) {
        #pragma unroll
        for (int nt = 0; nt < 8; nt++) {
            float* p0 = Cw + (size_t)(mt * 16 + g) * RDIM + nt * 8 + 2 * t;
            float* p1 = p0 + 8 * RDIM;
            *(float2*)p0 = make_float2(acc[mt][nt][0] * CORR, acc[mt][nt][1] * CORR);
            *(float2*)p1 = make_float2(acc[mt][nt][2] * CORR, acc[mt][nt][3] * CORR);
        }
    }
}

extern "C" void kernel_launch(void* const* d_in, const int* in_sizes, int n_in,
                              void* d_out, int out_size)
{
    const float* A = (const float*)d_in[0];  // matrix_1 [16,1024,256]
    const float* B = (const float*)d_in[1];  // matrix_2 [16,1024,256]
    float* C = (float*)d_out;                // [16,1024,1024]

    cudaFuncSetAttribute(bgemm_tf32_cpasync64_kernel,
                         cudaFuncAttributeMaxDynamicSharedMemorySize, SMEM_TOTAL);

    dim3 grid(RDIM / BN, RDIM / BM, BATCH);  // (4, 8, 16) = 512 CTAs
    bgemm_tf32_cpasync64_kernel<<<grid, NTHREADS, SMEM_TOTAL>>>(A, B, C);
}

// round 7
// speedup vs baseline: 1.1974x; 1.1974x over previous
#include <cuda_runtime.h>
#include <cstdint>

// Batched NT GEMM via tensor-core mma.sync (TF32) + cp.async pipeline:
//   C[b,i,j] = sum_d A[b,i,d] * B[b,j,d]
// A,B: [16,1024,256] f32 row-major, C: [16,1024,1024] f32.
//
// R5 config (proven fastest): CTA 128x128, BK=32, 3-stage cp.async ring,
// 8 warps (2M x 4N), warp tile 64x32, <=128 regs => 2 CTAs/SM (16 warps).
// R7 deltas: ldmatrix fragments double-buffered across kc (ldsm(kc+1)
// issued before mma(kc)); cp.async refill issued after the first ldsm
// batch so tensor work starts immediately after the barrier.
// Raw f32 in SMEM; HW mma truncates to TF32; epilogue scales by 1.0007047
// to cancel the truncation bias.

#define BATCH 16
#define RDIM  1024
#define DDIM  256

#define BM 128
#define BN 128
#define BK 32
#define STAGES 3
#define KTILES (DDIM / BK)   // 8
#define NTHREADS 256

#define STAGE_BYTES (BM * BK * 4)              // 16384 per operand per stage
#define B_BASE      (STAGES * STAGE_BYTES)     // 49152
#define SMEM_TOTAL  (2 * STAGES * STAGE_BYTES) // 98304

// TF32 truncation-bias correction: E[rel err] = 2^-10 * 0.5/(2 ln2) = 3.522e-4
// per element; products carry 2x => scale C by (1 + 7.047e-4).
#define CORR 1.0007047f

__device__ __forceinline__ uint32_t smem_u32(const void* p) {
    uint32_t a;
    asm("{ .reg .u64 t; cvta.to.shared.u64 t, %1; cvt.u32.u64 %0, t; }" : "=r"(a) : "l"(p));
    return a;
}

__device__ __forceinline__ void cp_async16(uint32_t dst, const void* src) {
    asm volatile("cp.async.cg.shared.global [%0], [%1], 16;" :: "r"(dst), "l"(src) : "memory");
}
__device__ __forceinline__ void cp_commit() {
    asm volatile("cp.async.commit_group;" ::: "memory");
}
__device__ __forceinline__ void cp_wait1() {
    asm volatile("cp.async.wait_group 1;" ::: "memory");
}

__device__ __forceinline__ void ldsm4(uint32_t* d, uint32_t addr) {
    asm volatile("ldmatrix.sync.aligned.m8n8.x4.shared.b16 {%0,%1,%2,%3}, [%4];"
                 : "=r"(d[0]), "=r"(d[1]), "=r"(d[2]), "=r"(d[3]) : "r"(addr));
}

__device__ __forceinline__ void mma_tf32(float* c, const uint32_t* a, const uint32_t* b) {
    asm volatile(
        "mma.sync.aligned.m16n8k8.row.col.f32.tf32.tf32.f32 "
        "{%0,%1,%2,%3}, {%4,%5,%6,%7}, {%8,%9}, {%0,%1,%2,%3};"
        : "+f"(c[0]), "+f"(c[1]), "+f"(c[2]), "+f"(c[3])
        : "r"(a[0]), "r"(a[1]), "r"(a[2]), "r"(a[3]), "r"(b[0]), "r"(b[1]));
}

__global__ void __launch_bounds__(NTHREADS, 2)
bgemm_tf32_r7_kernel(const float* __restrict__ A,
                     const float* __restrict__ B,
                     float* __restrict__ C)
{
    extern __shared__ char smem[];
    const uint32_t sb = smem_u32(smem);

    const int tid  = threadIdx.x;
    const int wid  = tid >> 5;
    const int lane = tid & 31;

    const int b  = blockIdx.z;
    const int m0 = blockIdx.y * BM;
    const int n0 = blockIdx.x * BN;

    // ---- cp.async loader constants ----
    const int lrow = tid >> 3;       // 0..31
    const int lc4  = tid & 7;        // 16B unit within 128B row
    const float* gA = A + ((size_t)b * RDIM + m0 + lrow) * DDIM + lc4 * 4;
    const float* gB = B + ((size_t)b * RDIM + n0 + lrow) * DDIM + lc4 * 4;
    const uint32_t swu = (uint32_t)(lc4 ^ (lrow & 7)) << 4;     // SW128
    const uint32_t sA0 = sb + lrow * 128 + swu;
    const uint32_t sB0 = sb + B_BASE + lrow * 128 + swu;

    // ---- MMA constants ----
    const int warp_m = (wid & 1) * 64;       // 2 warps along M
    const int warp_n = (wid >> 1) * 32;      // 4 warps along N
    const int q  = lane >> 3;
    const int r_ = lane & 31 >> 3;           // placeholder; recomputed below
    const int rr = lane & 7;
    const int a_moff = (q & 1) * 8 + rr;
    const int a_par  = q >> 1;
    const int b_noff = (q >> 1) * 8 + rr;
    const int b_par  = q & 1;
    const uint32_t aF0 = sb + (warp_m + a_moff) * 128;
    const uint32_t bF0 = sb + B_BASE + (warp_n + b_noff) * 128;

    float acc[4][4][4];
    #pragma unroll
    for (int i = 0; i < 4; i++)
        #pragma unroll
        for (int j = 0; j < 4; j++)
            #pragma unroll
            for (int k = 0; k < 4; k++)
                acc[i][j][k] = 0.0f;

    uint32_t af[2][4][4], bf[2][2][4];

#define ISSUE_STAGE(s, ko)                                                     \
    do {                                                                       \
        const uint32_t _a = sA0 + (s) * STAGE_BYTES;                           \
        const uint32_t _b = sB0 + (s) * STAGE_BYTES;                           \
        _Pragma("unroll")                                                      \
        for (int _i = 0; _i < 4; _i++) {                                       \
            cp_async16(_a + _i * 4096, gA + (size_t)_i * 32 * DDIM + (ko));    \
            cp_async16(_b + _i * 4096, gB + (size_t)_i * 32 * DDIM + (ko));    \
        }                                                                      \
    } while (0)

#define LD_FRAGS(p, aBase, bBase, kc)                                          \
    do {                                                                       \
        const uint32_t _ua = ((uint32_t)((2 * (kc) + a_par) ^ rr)) << 4;       \
        const uint32_t _ub = ((uint32_t)((2 * (kc) + b_par) ^ rr)) << 4;       \
        _Pragma("unroll")                                                      \
        for (int _mt = 0; _mt < 4; _mt++)                                      \
            ldsm4(af[p][_mt], (aBase) + _mt * 2048 + _ua);                     \
        _Pragma("unroll")                                                      \
        for (int _np = 0; _np < 2; _np++)                                      \
            ldsm4(bf[p][_np], (bBase) + _np * 2048 + _ub);                     \
    } while (0)

#define MMA_ALL(p)                                                             \
    do {                                                                       \
        _Pragma("unroll")                                                      \
        for (int _mt = 0; _mt < 4; _mt++)                                      \
            _Pragma("unroll")                                                  \
            for (int _nt = 0; _nt < 4; _nt++)                                  \
                mma_tf32(acc[_mt][_nt], af[p][_mt], &bf[p][_nt >> 1][(_nt & 1) * 2]); \
    } while (0)

    // ---- prologue: stages 0,1 in flight ----
    ISSUE_STAGE(0, 0);
    cp_commit();
    ISSUE_STAGE(1, BK);
    cp_commit();

    int s = 0;
    for (int kt = 0; kt < KTILES; kt++) {
        cp_wait1();          // stage kt landed
        __syncthreads();     // visible to all warps; stage (kt-1) fully consumed

        const uint32_t aBase = aF0 + s * STAGE_BYTES;
        const uint32_t bBase = bF0 + s * STAGE_BYTES;

        // start fragment loads FIRST so tensor work begins ASAP...
        LD_FRAGS(0, aBase, bBase, 0);

        // ...then issue the next stage's cp.asyncs (latency-hidden by MMAs)
        if (kt < KTILES - 2)
            ISSUE_STAGE((kt + 2) % STAGES, (kt + 2) * BK);
        cp_commit();         // uniform group count (empty groups are legal)

        // software-pipelined: ldsm(kc+1) issued before mma(kc)
        #pragma unroll
        for (int kc = 0; kc < 4; kc++) {
            if (kc < 3)
                LD_FRAGS((kc + 1) & 1, aBase, bBase, kc + 1);
            MMA_ALL(kc & 1);
        }

        s = (s + 1 == STAGES) ? 0 : s + 1;
    }

    // ---- epilogue: bias-corrected stores ----
    const int g = lane >> 2;
    const int t = lane & 3;
    float* Cw = C + (size_t)b * RDIM * RDIM + (size_t)(m0 + warp_m) * RDIM + n0 + warp_n;

    #pragma unroll
    for (int mt = 0; mt < 4; mt++) {
        #pragma unroll
        for (int nt = 0; nt < 4; nt++) {
            float* p0 = Cw + (size_t)(mt * 16 + g) * RDIM + nt * 8 + 2 * t;
            float* p1 = p0 + 8 * RDIM;
            *(float2*)p0 = make_float2(acc[mt][nt][0] * CORR, acc[mt][nt][1] * CORR);
            *(float2*)p1 = make_float2(acc[mt][nt][2] * CORR, acc[mt][nt][3] * CORR);
        }
    }
}

extern "C" void kernel_launch(void* const* d_in, const int* in_sizes, int n_in,
                              void* d_out, int out_size)
{
    const float* A = (const float*)d_in[0];  // matrix_1 [16,1024,256]
    const float* B = (const float*)d_in[1];  // matrix_2 [16,1024,256]
    float* C = (float*)d_out;                // [16,1024,1024]

    cudaFuncSetAttribute(bgemm_tf32_r7_kernel,
                         cudaFuncAttributeMaxDynamicSharedMemorySize, SMEM_TOTAL);

    dim3 grid(RDIM / BN, RDIM / BM, BATCH);  // (8, 8, 16) = 1024 CTAs
    bgemm_tf32_r7_kernel<<<grid, NTHREADS, SMEM_TOTAL>>>(A, B, C);
}

// round 8
// speedup vs baseline: 1.2460x; 1.0406x over previous
#include <cuda_runtime.h>
#include <cstdint>

// Batched NT GEMM via tensor-core mma.sync (TF32) + persistent cp.async pipeline:
//   C[b,i,j] = sum_d A[b,i,d] * B[b,j,d]
// A,B: [16,1024,256] f32 row-major, C: [16,1024,1024] f32.
//
// R5 config (proven): CTA 128x128, BK=32, 3-stage cp.async ring, 8 warps
// (2M x 4N), warp tile 64x32, <=128 regs => 2 CTAs/SM.
// R8 delta: persistent CTAs; the cp.async stage ring runs CONTINUOUSLY across
// tiles (refills during kt=6,7 of tile t feed kt=0,1 of tile t+stride), so the
// pipeline never drains and the epilogue overlaps the next tile's loads.
// Raw f32 in SMEM; HW mma truncates to TF32; epilogue scales by 1.0007047.

#define BATCH 16
#define RDIM  1024
#define DDIM  256

#define BM 128
#define BN 128
#define BK 32
#define STAGES 3
#define KTILES (DDIM / BK)   // 8
#define NTHREADS 256
#define NTILES  (BATCH * (RDIM / BM) * (RDIM / BN))   // 1024
#define GRIDC   304                                   // 2 * 152 SMs

#define STAGE_BYTES (BM * BK * 4)              // 16384 per operand per stage
#define B_BASE      (STAGES * STAGE_BYTES)     // 49152
#define SMEM_TOTAL  (2 * STAGES * STAGE_BYTES) // 98304

// TF32 truncation-bias correction: E[rel err] = 2^-10 * 0.5/(2 ln2) = 3.522e-4
// per element; products carry 2x => scale C by (1 + 7.047e-4).
#define CORR 1.0007047f

__device__ __forceinline__ uint32_t smem_u32(const void* p) {
    uint32_t a;
    asm("{ .reg .u64 t; cvta.to.shared.u64 t, %1; cvt.u32.u64 %0, t; }" : "=r"(a) : "l"(p));
    return a;
}

__device__ __forceinline__ void cp_async16(uint32_t dst, const void* src) {
    asm volatile("cp.async.cg.shared.global [%0], [%1], 16;" :: "r"(dst), "l"(src) : "memory");
}
__device__ __forceinline__ void cp_commit() {
    asm volatile("cp.async.commit_group;" ::: "memory");
}
__device__ __forceinline__ void cp_wait1() {
    asm volatile("cp.async.wait_group 1;" ::: "memory");
}

__device__ __forceinline__ void ldsm4(uint32_t* d, uint32_t addr) {
    asm volatile("ldmatrix.sync.aligned.m8n8.x4.shared.b16 {%0,%1,%2,%3}, [%4];"
                 : "=r"(d[0]), "=r"(d[1]), "=r"(d[2]), "=r"(d[3]) : "r"(addr));
}

__device__ __forceinline__ void mma_tf32(float* c, const uint32_t* a, const uint32_t* b) {
    asm volatile(
        "mma.sync.aligned.m16n8k8.row.col.f32.tf32.tf32.f32 "
        "{%0,%1,%2,%3}, {%4,%5,%6,%7}, {%8,%9}, {%0,%1,%2,%3};"
        : "+f"(c[0]), "+f"(c[1]), "+f"(c[2]), "+f"(c[3])
        : "r"(a[0]), "r"(a[1]), "r"(a[2]), "r"(a[3]), "r"(b[0]), "r"(b[1]));
}

__global__ void __launch_bounds__(NTHREADS, 2)
bgemm_tf32_persist_kernel(const float* __restrict__ A,
                          const float* __restrict__ B,
                          float* __restrict__ C)
{
    extern __shared__ char smem[];
    const uint32_t sb = smem_u32(smem);

    const int tid  = threadIdx.x;
    const int wid  = tid >> 5;
    const int lane = tid & 31;

    // ---- cp.async loader constants (tile-independent) ----
    const int lrow = tid >> 3;       // 0..31
    const int lc4  = tid & 7;        // 16B unit within 128B row
    const uint32_t swu = (uint32_t)(lc4 ^ (lrow & 7)) << 4;     // SW128
    const uint32_t sA0 = sb + lrow * 128 + swu;
    const uint32_t sB0 = sb + B_BASE + lrow * 128 + swu;
    const size_t lOffA = (size_t)lrow * DDIM + lc4 * 4;         // within tile block

    // ---- MMA constants ----
    const int warp_m = (wid & 1) * 64;       // 2 warps along M
    const int warp_n = (wid >> 1) * 32;      // 4 warps along N
    const int q  = lane >> 3;
    const int rr = lane & 7;
    const int a_moff = (q & 1) * 8 + rr;
    const int a_par  = q >> 1;
    const int b_noff = (q >> 1) * 8 + rr;
    const int b_par  = q & 1;
    const uint32_t aF0 = sb + (warp_m + a_moff) * 128;
    const uint32_t bF0 = sb + B_BASE + (warp_n + b_noff) * 128;

    // tile index -> global pointers for this thread's cp.async lane
#define TILE_PTRS(t, pa, pb)                                                   \
    do {                                                                       \
        const int _bz = (t) >> 6;                                              \
        const int _by = ((t) >> 3) & 7;                                        \
        const int _bx = (t) & 7;                                               \
        (pa) = A + ((size_t)_bz * RDIM + _by * BM) * DDIM + lOffA;             \
        (pb) = B + ((size_t)_bz * RDIM + _bx * BN) * DDIM + lOffA;             \
    } while (0)

#define ISSUE_STAGE_P(s, pa, pb, ko)                                           \
    do {                                                                       \
        const uint32_t _a = sA0 + (s) * STAGE_BYTES;                           \
        const uint32_t _b = sB0 + (s) * STAGE_BYTES;                           \
        _Pragma("unroll")                                                      \
        for (int _i = 0; _i < 4; _i++) {                                       \
            cp_async16(_a + _i * 4096, (pa) + (size_t)_i * 32 * DDIM + (ko));  \
            cp_async16(_b + _i * 4096, (pb) + (size_t)_i * 32 * DDIM + (ko));  \
        }                                                                      \
    } while (0)

    float acc[4][4][4];
    #pragma unroll
    for (int i = 0; i < 4; i++)
        #pragma unroll
        for (int j = 0; j < 4; j++)
            #pragma unroll
            for (int k = 0; k < 4; k++)
                acc[i][j][k] = 0.0f;

    int t = blockIdx.x;
    if (t >= NTILES) return;

    const float *gAc, *gBc, *gAn, *gBn;
    TILE_PTRS(t, gAc, gBc);

    // ---- prologue: stages 0,1 of the first tile in flight ----
    ISSUE_STAGE_P(0, gAc, gBc, 0);
    cp_commit();
    ISSUE_STAGE_P(1, gAc, gBc, BK);
    cp_commit();

    int s = 0;
    for (; t < NTILES; t += GRIDC) {
        const int tn = t + GRIDC;
        const bool has_next = tn < NTILES;
        if (has_next) TILE_PTRS(tn, gAn, gBn);

        for (int kt = 0; kt < KTILES; kt++) {
            cp_wait1();          // stage for this kt landed
            __syncthreads();     // visible to all; stage (kt-1) fully consumed

            const uint32_t aBase = aF0 + s * STAGE_BYTES;
            const uint32_t bBase = bF0 + s * STAGE_BYTES;

            // refill: j = kt+2 within current tile, else kt 0,1 of next tile
            const int j = kt + 2;
            const int sf = (s + 2 >= STAGES) ? (s + 2 - STAGES) : (s + 2);
            if (j < KTILES) {
                ISSUE_STAGE_P(sf, gAc, gBc, j * BK);
            } else if (has_next) {
                ISSUE_STAGE_P(sf, gAn, gBn, (j - KTILES) * BK);
            }
            cp_commit();         // uniform group count (empty groups are legal)

            #pragma unroll
            for (int kc = 0; kc < 4; kc++) {
                const uint32_t ua = ((uint32_t)((2 * kc + a_par) ^ rr)) << 4;
                const uint32_t ub = ((uint32_t)((2 * kc + b_par) ^ rr)) << 4;
                uint32_t af[4][4], bf[2][4];
                #pragma unroll
                for (int mt = 0; mt < 4; mt++) ldsm4(af[mt], aBase + mt * 2048 + ua);
                #pragma unroll
                for (int np = 0; np < 2; np++) ldsm4(bf[np], bBase + np * 2048 + ub);
                #pragma unroll
                for (int mt = 0; mt < 4; mt++)
                    #pragma unroll
                    for (int nt = 0; nt < 4; nt++)
                        mma_tf32(acc[mt][nt], af[mt], &bf[nt >> 1][(nt & 1) * 2]);
            }

            s = (s + 1 == STAGES) ? 0 : s + 1;
        }

        // ---- epilogue for tile t (next tile's stages already in flight) ----
        {
            const int bz = t >> 6;
            const int by = (t >> 3) & 7;
            const int bx = t & 7;
            const int g  = lane >> 2;
            const int tt = lane & 3;
            float* Cw = C + (size_t)bz * RDIM * RDIM
                          + (size_t)(by * BM + warp_m) * RDIM + bx * BN + warp_n;
            #pragma unroll
            for (int mt = 0; mt < 4; mt++) {
                #pragma unroll
                for (int nt = 0; nt < 4; nt++) {
                    float* p0 = Cw + (size_t)(mt * 16 + g) * RDIM + nt * 8 + 2 * tt;
                    float* p1 = p0 + 8 * RDIM;
                    *(float2*)p0 = make_float2(acc[mt][nt][0] * CORR, acc[mt][nt][1] * CORR);
                    *(float2*)p1 = make_float2(acc[mt][nt][2] * CORR, acc[mt][nt][3] * CORR);
                    acc[mt][nt][0] = 0.0f; acc[mt][nt][1] = 0.0f;
                    acc[mt][nt][2] = 0.0f; acc[mt][nt][3] = 0.0f;
                }
            }
        }

        gAc = gAn;
        gBc = gBn;
    }
}

extern "C" void kernel_launch(void* const* d_in, const int* in_sizes, int n_in,
                              void* d_out, int out_size)
{
    const float* A = (const float*)d_in[0];  // matrix_1 [16,1024,256]
    const float* B = (const float*)d_in[1];  // matrix_2 [16,1024,256]
    float* C = (float*)d_out;                // [16,1024,1024]

    cudaFuncSetAttribute(bgemm_tf32_persist_kernel,
                         cudaFuncAttributeMaxDynamicSharedMemorySize, SMEM_TOTAL);

    bgemm_tf32_persist_kernel<<<GRIDC, NTHREADS, SMEM_TOTAL>>>(A, B, C);
}

// round 10
// speedup vs baseline: 1.2664x; 1.0164x over previous
#include <cuda_runtime.h>
#include <cstdint>

// Batched NT GEMM via tensor-core mma.sync (TF32) + mbarrier free-run pipeline:
//   C[b,i,j] = sum_d A[b,i,d] * B[b,j,d]
// A,B: [16,1024,256] f32 row-major, C: [16,1024,1024] f32.
//
// Core config (proven R5): CTA 128x128, BK=32, 3-stage cp.async ring, 8 warps
// (2M x 4N), warp tile 64x32, 2 CTAs/SM. No per-kt __syncthreads:
// full[s] mbarriers (count 256, cp.async.mbarrier.arrive.NOINC) gate consumers;
// empty[s] mbarriers (count 8, one arrive/warp after its MMAs) gate producers.
// R10 fix vs R9: .noinc on the cp.async arrive — without it the async arrive
// only consumes its own synchronous increment and the base count never drains
// (deadlock observed as the 120s timeout).
// Persistent CTAs keep the ring filled across tiles.
// Raw f32 in SMEM; HW mma truncates to TF32; epilogue scales by 1.0007047.

#define BATCH 16
#define RDIM  1024
#define DDIM  256

#define BM 128
#define BN 128
#define BK 32
#define STAGES 3
#define KTILES (DDIM / BK)   // 8
#define NTHREADS 256
#define NTILES  (BATCH * (RDIM / BM) * (RDIM / BN))   // 1024
#define GRIDC   304                                   // 2 * 152 SMs

#define STAGE_BYTES (BM * BK * 4)              // 16384 per operand per stage
#define B_BASE      (STAGES * STAGE_BYTES)     // 49152
#define MB_OFF      (2 * STAGES * STAGE_BYTES) // 98304
#define SMEM_TOTAL  (MB_OFF + 64)              // 98368

// TF32 truncation-bias correction: E[rel err] = 2^-10 * 0.5/(2 ln2) = 3.522e-4
// per element; products carry 2x => scale C by (1 + 7.047e-4).
#define CORR 1.0007047f

__device__ __forceinline__ uint32_t smem_u32(const void* p) {
    uint32_t a;
    asm("{ .reg .u64 t; cvta.to.shared.u64 t, %1; cvt.u32.u64 %0, t; }" : "=r"(a) : "l"(p));
    return a;
}

__device__ __forceinline__ void cp_async16(uint32_t dst, const void* src) {
    asm volatile("cp.async.cg.shared.global [%0], [%1], 16;" :: "r"(dst), "l"(src) : "memory");
}

__device__ __forceinline__ void mbar_init(uint32_t mbar, uint32_t count) {
    asm volatile("mbarrier.init.shared.b64 [%0], %1;" :: "r"(mbar), "r"(count) : "memory");
}
__device__ __forceinline__ void mbar_arrive(uint32_t mbar) {
    asm volatile("mbarrier.arrive.shared.b64 _, [%0];" :: "r"(mbar) : "memory");
}
// Arrive when ALL of this thread's prior cp.asyncs complete; .noinc counts the
// async arrival against the barrier's base expected count.
__device__ __forceinline__ void cp_arrive_noinc(uint32_t mbar) {
    asm volatile("cp.async.mbarrier.arrive.noinc.shared.b64 [%0];" :: "r"(mbar) : "memory");
}
__device__ __forceinline__ void mbar_wait(uint32_t mbar, uint32_t parity) {
    asm volatile(
        "{\n\t"
        ".reg .pred P;\n\t"
        "WAIT_%=:\n\t"
        "mbarrier.try_wait.parity.acquire.cta.shared::cta.b64 P, [%0], %1, 0x989680;\n\t"
        "@P bra DONE_%=;\n\t"
        "bra WAIT_%=;\n\t"
        "DONE_%=:\n\t"
        "}"
        :: "r"(mbar), "r"(parity) : "memory");
}

__device__ __forceinline__ void ldsm4(uint32_t* d, uint32_t addr) {
    asm volatile("ldmatrix.sync.aligned.m8n8.x4.shared.b16 {%0,%1,%2,%3}, [%4];"
                 : "=r"(d[0]), "=r"(d[1]), "=r"(d[2]), "=r"(d[3]) : "r"(addr));
}

__device__ __forceinline__ void mma_tf32(float* c, const uint32_t* a, const uint32_t* b) {
    asm volatile(
        "mma.sync.aligned.m16n8k8.row.col.f32.tf32.tf32.f32 "
        "{%0,%1,%2,%3}, {%4,%5,%6,%7}, {%8,%9}, {%0,%1,%2,%3};"
        : "+f"(c[0]), "+f"(c[1]), "+f"(c[2]), "+f"(c[3])
        : "r"(a[0]), "r"(a[1]), "r"(a[2]), "r"(a[3]), "r"(b[0]), "r"(b[1]));
}

__global__ void __launch_bounds__(NTHREADS, 2)
bgemm_tf32_mbar2_kernel(const float* __restrict__ A,
                        const float* __restrict__ B,
                        float* __restrict__ C)
{
    extern __shared__ char smem[];
    const uint32_t sb = smem_u32(smem);

    const int tid  = threadIdx.x;
    const int wid  = tid >> 5;
    const int lane = tid & 31;

    const uint32_t fullb  = sb + MB_OFF;        // full[s]  = fullb  + s*8
    const uint32_t emptyb = sb + MB_OFF + 32;   // empty[s] = emptyb + s*8

    // ---- cp.async loader constants (tile-independent) ----
    const int lrow = tid >> 3;       // 0..31
    const int lc4  = tid & 7;        // 16B unit within 128B row
    const uint32_t swu = (uint32_t)(lc4 ^ (lrow & 7)) << 4;     // SW128
    const uint32_t sA0 = sb + lrow * 128 + swu;
    const uint32_t sB0 = sb + B_BASE + lrow * 128 + swu;
    const size_t lOffA = (size_t)lrow * DDIM + lc4 * 4;

    // ---- MMA constants ----
    const int warp_m = (wid & 1) * 64;       // 2 warps along M
    const int warp_n = (wid >> 1) * 32;      // 4 warps along N
    const int q  = lane >> 3;
    const int rr = lane & 7;
    const int a_moff = (q & 1) * 8 + rr;
    const int a_par  = q >> 1;
    const int b_noff = (q >> 1) * 8 + rr;
    const int b_par  = q & 1;
    const uint32_t aF0 = sb + (warp_m + a_moff) * 128;
    const uint32_t bF0 = sb + B_BASE + (warp_n + b_noff) * 128;

#define TILE_PTRS(t, pa, pb)                                                   \
    do {                                                                       \
        const int _bz = (t) >> 6;                                              \
        const int _by = ((t) >> 3) & 7;                                        \
        const int _bx = (t) & 7;                                               \
        (pa) = A + ((size_t)_bz * RDIM + _by * BM) * DDIM + lOffA;             \
        (pb) = B + ((size_t)_bz * RDIM + _bx * BN) * DDIM + lOffA;             \
    } while (0)

    // produce: wait empty[sp] (parity pp), issue 8 cp.asyncs, async-arrive full[sp]
#define PRODUCE(pa, pb, ko)                                                    \
    do {                                                                       \
        mbar_wait(emptyb + sp * 8, pp);                                        \
        const uint32_t _a = sA0 + sp * STAGE_BYTES;                            \
        const uint32_t _b = sB0 + sp * STAGE_BYTES;                            \
        _Pragma("unroll")                                                      \
        for (int _i = 0; _i < 4; _i++) {                                       \
            cp_async16(_a + _i * 4096, (pa) + (size_t)_i * 32 * DDIM + (ko));  \
            cp_async16(_b + _i * 4096, (pb) + (size_t)_i * 32 * DDIM + (ko));  \
        }                                                                      \
        cp_arrive_noinc(fullb + sp * 8);                                       \
        sp = (sp + 1 == STAGES) ? 0 : sp + 1;                                  \
        if (sp == 0) pp ^= 1;                                                  \
    } while (0)

    // ---- barrier init ----
    if (tid == 0) {
        #pragma unroll
        for (int s = 0; s < STAGES; s++) {
            mbar_init(fullb + s * 8, NTHREADS);   // 256 async arrives (.noinc)
            mbar_init(emptyb + s * 8, 8);         // 8 warp arrives
        }
    }
    __syncthreads();   // only CTA-wide barrier in the kernel

    float acc[4][4][4];
    #pragma unroll
    for (int i = 0; i < 4; i++)
        #pragma unroll
        for (int j = 0; j < 4; j++)
            #pragma unroll
            for (int k = 0; k < 4; k++)
                acc[i][j][k] = 0.0f;

    int t = blockIdx.x;
    const float *gAc, *gBc, *gAn, *gBn;
    TILE_PTRS(t, gAc, gBc);

    int sp = 0, pp = 1;   // producer cursor (first empty-waits pass immediately)
    int sc = 0, pc = 0;   // consumer cursor

    // prologue: 2 stages of the first tile in flight
    PRODUCE(gAc, gBc, 0);
    PRODUCE(gAc, gBc, BK);

    for (; t < NTILES; t += GRIDC) {
        const int tn = t + GRIDC;
        const bool has_next = tn < NTILES;
        if (has_next) TILE_PTRS(tn, gAn, gBn);

        for (int kt = 0; kt < KTILES; kt++) {
            // ---- consume stage sc ----
            mbar_wait(fullb + sc * 8, pc);
            const uint32_t aBase = aF0 + sc * STAGE_BYTES;
            const uint32_t bBase = bF0 + sc * STAGE_BYTES;

            #pragma unroll
            for (int kc = 0; kc < 4; kc++) {
                const uint32_t ua = ((uint32_t)((2 * kc + a_par) ^ rr)) << 4;
                const uint32_t ub = ((uint32_t)((2 * kc + b_par) ^ rr)) << 4;
                uint32_t af[4][4], bf[2][4];
                #pragma unroll
                for (int mt = 0; mt < 4; mt++) ldsm4(af[mt], aBase + mt * 2048 + ua);
                #pragma unroll
                for (int np = 0; np < 2; np++) ldsm4(bf[np], bBase + np * 2048 + ub);
                #pragma unroll
                for (int mt = 0; mt < 4; mt++)
                    #pragma unroll
                    for (int nt = 0; nt < 4; nt++)
                        mma_tf32(acc[mt][nt], af[mt], &bf[nt >> 1][(nt & 1) * 2]);
            }

            // release stage sc (all this warp's ldsm reads have completed:
            // their results were consumed by the MMAs above)
            if (lane == 0) mbar_arrive(emptyb + sc * 8);
            sc = (sc + 1 == STAGES) ? 0 : sc + 1;
            if (sc == 0) pc ^= 1;

            // ---- produce stage for kt+2 ----
            const int j = kt + 2;
            if (j < KTILES) {
                PRODUCE(gAc, gBc, j * BK);
            } else if (has_next) {
                PRODUCE(gAn, gBn, (j - KTILES) * BK);
            }
        }

        // ---- epilogue for tile t (next tile's stages already in flight) ----
        {
            const int bz = t >> 6;
            const int by = (t >> 3) & 7;
            const int bx = t & 7;
            const int g  = lane >> 2;
            const int tt = lane & 3;
            float* Cw = C + (size_t)bz * RDIM * RDIM
                          + (size_t)(by * BM + warp_m) * RDIM + bx * BN + warp_n;
            #pragma unroll
            for (int mt = 0; mt < 4; mt++) {
                #pragma unroll
                for (int nt = 0; nt < 4; nt++) {
                    float* p0 = Cw + (size_t)(mt * 16 + g) * RDIM + nt * 8 + 2 * tt;
                    float* p1 = p0 + 8 * RDIM;
                    *(float2*)p0 = make_float2(acc[mt][nt][0] * CORR, acc[mt][nt][1] * CORR);
                    *(float2*)p1 = make_float2(acc[mt][nt][2] * CORR, acc[mt][nt][3] * CORR);
                    acc[mt][nt][0] = 0.0f; acc[mt][nt][1] = 0.0f;
                    acc[mt][nt][2] = 0.0f; acc[mt][nt][3] = 0.0f;
                }
            }
        }

        gAc = gAn;
        gBc = gBn;
    }
}

extern "C" void kernel_launch(void* const* d_in, const int* in_sizes, int n_in,
                              void* d_out, int out_size)
{
    const float* A = (const float*)d_in[0];  // matrix_1 [16,1024,256]
    const float* B = (const float*)d_in[1];  // matrix_2 [16,1024,256]
    float* C = (float*)d_out;                // [16,1024,1024]

    cudaFuncSetAttribute(bgemm_tf32_mbar2_kernel,
                         cudaFuncAttributeMaxDynamicSharedMemorySize, SMEM_TOTAL);

    bgemm_tf32_mbar2_kernel<<<GRIDC, NTHREADS, SMEM_TOTAL>>>(A, B, C);
}